// round 10
// baseline (speedup 1.0000x reference)
#include <cuda_runtime.h>

// Sinkhorn: 65536 matrices of 36x36, 21 iterations of row/col log-normalization,
// temperature 0.01, output exp(log_alpha).
//
// Base-2 potential form: matrix = y - U_i - V_j, y = input * (100*log2 e).
//   row pass: U_i = lse2_j(y_ij - V_j);  col pass: V_j = lse2_i(y_ij - U_i)
// start V=0; after 21 (row,col) pairs, out = 2^(y - U - V).
//
// R10 = R9 (3 blocks/SM, no yreg, smem-fed t[36], exact max every pass)
//     + MUFU/FMA pipe split: 8 of 36 exps per pass via FMA-pipe polynomial
//       exp2 (soft_ex2). R8 showed the split loses at occ 2 (exposed FMA
//       chain latency); at 6.75 warps/SMSP the chain is covered and the MUFU
//       bound drops 37->29 ops/pass. Register budget is the hard constraint:
//       must stay <= 75 to hold 3 blocks/SM without spills.

#define NMAT_PER_BLOCK 8
#define THREADS 288            // 8 groups * 36 = 9 full warps
#define NDIM 36
#define STRIDE 37              // 37 mod 32 = 5 -> conflict-free rows & cols
#define MAT_SMEM (NDIM * STRIDE)
#define MAT_ELEMS (NDIM * NDIM)
#define SCALE 144.269504088896340736f   // 100 * log2(e)
#define NITERS 21
#define NSOFT 8                // exps routed to the FMA pipe per pass
#define MAGIC 12582912.0f      // 1.5 * 2^23

__device__ __forceinline__ float ex2f(float x) {
    float y; asm("ex2.approx.ftz.f32 %0, %1;" : "=f"(y) : "f"(x)); return y;
}
__device__ __forceinline__ float lg2f(float x) {
    float y; asm("lg2.approx.ftz.f32 %0, %1;" : "=f"(y) : "f"(x)); return y;
}

// FMA-pipe exp2 for x <= 0 (post max-subtract), clamped at -126.
// rint via magic add, degree-5 poly on [-0.5,0.5], exponent splice via
// integer add (low 9 bits of bits(MAGIC) are zero so (bits(t)<<23) == n<<23
// mod 2^32). Max rel err ~2.4e-6. 10 instrs, all fma/alu pipe — zero MUFU.
__device__ __forceinline__ float soft_ex2(float x) {
    x = fmaxf(x, -126.0f);
    float t = __fadd_rn(x, MAGIC);
    float n = __fadd_rn(t, -MAGIC);
    float f = x - n;                          // [-0.5, 0.5]
    float p =            1.3333558e-3f;
    p = __fmaf_rn(p, f, 9.6181291e-3f);
    p = __fmaf_rn(p, f, 5.5504109e-2f);
    p = __fmaf_rn(p, f, 2.4022651e-1f);
    p = __fmaf_rn(p, f, 6.9314718e-1f);
    p = __fmaf_rn(p, f, 1.0f);
    return __int_as_float(__float_as_int(p) + (__float_as_int(t) << 23));
}

__global__ __launch_bounds__(THREADS, 3)
void sinkhorn_kernel(const float* __restrict__ in, float* __restrict__ out)
{
    __shared__ float sy[NMAT_PER_BLOCK * MAT_SMEM];   // padded matrices (base-2 scaled)
    __shared__ __align__(16) float sU[NMAT_PER_BLOCK * NDIM];
    __shared__ __align__(16) float sV[NMAT_PER_BLOCK * NDIM];

    const int tid = threadIdx.x;
    const long long base = (long long)blockIdx.x * (NMAT_PER_BLOCK * MAT_ELEMS);

    // ---- load: coalesced float4 from global, scatter into padded smem, fused scale
    {
        const float4* in4 = (const float4*)(in + base);
        for (int k = tid; k < (NMAT_PER_BLOCK * MAT_ELEMS) / 4; k += THREADS) {
            float4 v = in4[k];
            float vals[4] = {v.x, v.y, v.z, v.w};
            int e = k * 4;
            #pragma unroll
            for (int q = 0; q < 4; q++) {
                int idx = e + q;
                int g   = idx / MAT_ELEMS;
                int rem = idx - g * MAT_ELEMS;
                int r   = rem / NDIM;
                int c   = rem - r * NDIM;
                sy[g * MAT_SMEM + r * STRIDE + c] = vals[q] * SCALE;
            }
        }
    }
    sV[tid] = 0.0f;                       // 288 == THREADS
    __syncthreads();

    const int g = tid / NDIM;          // which matrix in this block
    const int l = tid - g * NDIM;      // row (row pass) / col (col pass) index

    const float4* U4 = (const float4*)&sU[g * NDIM];
    const float4* V4 = (const float4*)&sV[g * NDIM];
    float* U = &sU[g * NDIM];
    float* V = &sV[g * NDIM];
    const float* srow = &sy[g * MAT_SMEM + l * STRIDE];
    const float* scol = &sy[g * MAT_SMEM + l];

    #pragma unroll 1
    for (int it = 0; it < NITERS; it++) {
        // ---- row pass: U[l] = m + log2(sum_j 2^(srow[j] - V[j] - m))
        {
            float t[NDIM];
            float m0 = -1e30f, m1 = -1e30f, m2 = -1e30f, m3 = -1e30f;
            #pragma unroll
            for (int q = 0; q < 9; q++) {
                float4 v = V4[q];                 // broadcast across the group
                t[4*q+0] = srow[4*q+0] - v.x;
                t[4*q+1] = srow[4*q+1] - v.y;
                t[4*q+2] = srow[4*q+2] - v.z;
                t[4*q+3] = srow[4*q+3] - v.w;
                m0 = fmaxf(m0, t[4*q+0]);  m1 = fmaxf(m1, t[4*q+1]);
                m2 = fmaxf(m2, t[4*q+2]);  m3 = fmaxf(m3, t[4*q+3]);
            }
            float m = fmaxf(fmaxf(m0, m1), fmaxf(m2, m3));
            float a0 = 0.f, a1 = 0.f;                    // FMA-pipe accumulators
            #pragma unroll
            for (int j = 0; j < NSOFT; j += 2) {
                a0 += soft_ex2(t[j]   - m);
                a1 += soft_ex2(t[j+1] - m);
            }
            float s0 = 0.f, s1 = 0.f, s2 = 0.f, s3 = 0.f; // MUFU accumulators
            #pragma unroll
            for (int j = NSOFT; j < NDIM; j += 4) {
                s0 += ex2f(t[j]   - m);
                s1 += ex2f(t[j+1] - m);
                s2 += ex2f(t[j+2] - m);
                s3 += ex2f(t[j+3] - m);
            }
            U[l] = m + lg2f(((a0 + a1) + (s0 + s1)) + (s2 + s3));
        }
        __syncthreads();

        // ---- col pass: V[l] = m + log2(sum_i 2^(scol[i*37] - U[i] - m))
        {
            float t[NDIM];
            float m0 = -1e30f, m1 = -1e30f, m2 = -1e30f, m3 = -1e30f;
            #pragma unroll
            for (int q = 0; q < 9; q++) {
                float4 u = U4[q];                 // broadcast across the group
                t[4*q+0] = scol[(4*q+0) * STRIDE] - u.x;
                t[4*q+1] = scol[(4*q+1) * STRIDE] - u.y;
                t[4*q+2] = scol[(4*q+2) * STRIDE] - u.z;
                t[4*q+3] = scol[(4*q+3) * STRIDE] - u.w;
                m0 = fmaxf(m0, t[4*q+0]);  m1 = fmaxf(m1, t[4*q+1]);
                m2 = fmaxf(m2, t[4*q+2]);  m3 = fmaxf(m3, t[4*q+3]);
            }
            float m = fmaxf(fmaxf(m0, m1), fmaxf(m2, m3));
            float a0 = 0.f, a1 = 0.f;
            #pragma unroll
            for (int i = 0; i < NSOFT; i += 2) {
                a0 += soft_ex2(t[i]   - m);
                a1 += soft_ex2(t[i+1] - m);
            }
            float s0 = 0.f, s1 = 0.f, s2 = 0.f, s3 = 0.f;
            #pragma unroll
            for (int i = NSOFT; i < NDIM; i += 4) {
                s0 += ex2f(t[i]   - m);
                s1 += ex2f(t[i+1] - m);
                s2 += ex2f(t[i+2] - m);
                s3 += ex2f(t[i+3] - m);
            }
            V[l] = m + lg2f(((a0 + a1) + (s0 + s1)) + (s2 + s3));
        }
        __syncthreads();
    }

    // ---- output: overwrite my row of sy with 2^(y - U - V), pipe-split
    {
        const float u = U[l];
        float* od = &sy[g * MAT_SMEM + l * STRIDE];
        #pragma unroll
        for (int q = 0; q < 9; q++) {
            float4 v = V4[q];
            float r0, r1, r2, r3;
            if (q < NSOFT / 4) {
                r0 = soft_ex2((od[4*q+0] - u) - v.x);
                r1 = soft_ex2((od[4*q+1] - u) - v.y);
                r2 = soft_ex2((od[4*q+2] - u) - v.z);
                r3 = soft_ex2((od[4*q+3] - u) - v.w);
            } else {
                r0 = ex2f((od[4*q+0] - u) - v.x);
                r1 = ex2f((od[4*q+1] - u) - v.y);
                r2 = ex2f((od[4*q+2] - u) - v.z);
                r3 = ex2f((od[4*q+3] - u) - v.w);
            }
            od[4*q+0] = r0; od[4*q+1] = r1; od[4*q+2] = r2; od[4*q+3] = r3;
        }
    }
    __syncthreads();
    {
        float4* out4 = (float4*)(out + base);
        for (int k = tid; k < (NMAT_PER_BLOCK * MAT_ELEMS) / 4; k += THREADS) {
            int e = k * 4;
            float r[4];
            #pragma unroll
            for (int q = 0; q < 4; q++) {
                int idx = e + q;
                int gg  = idx / MAT_ELEMS;
                int rem = idx - gg * MAT_ELEMS;
                int rr  = rem / NDIM;
                int cc  = rem - rr * NDIM;
                r[q] = sy[gg * MAT_SMEM + rr * STRIDE + cc];
            }
            out4[k] = make_float4(r[0], r[1], r[2], r[3]);
        }
    }
}

extern "C" void kernel_launch(void* const* d_in, const int* in_sizes, int n_in,
                              void* d_out, int out_size) {
    const float* in = (const float*)d_in[0];
    float* out = (float*)d_out;
    int num_mats = in_sizes[0] / MAT_ELEMS;          // 65536
    int grid = num_mats / NMAT_PER_BLOCK;            // 8192
    sinkhorn_kernel<<<grid, THREADS>>>(in, out);
}